// round 2
// baseline (speedup 1.0000x reference)
#include <cuda_runtime.h>
#include <math.h>

// Problem constants
#define BB 8192
#define NN 256
#define HH 2048
#define N2 512
#define LOG2PI 1.8378770664093453f

// Scratch (static __device__ — no runtime allocation)
__device__ float g_h[BB * HH];      // 64 MB  tanh(x@W1+b1)
__device__ float g_f[BB * N2];      // 16 MB  [mu | logvar]
__device__ float g_ux[BB * NN];     //  8 MB  x@Wv
__device__ float g_umu[BB * NN];    //  8 MB  mu@Wv
__device__ float g_Vx[BB];
__device__ float g_Vmu[BB];
__device__ float g_rowlogp[BB];

// ---------------------------------------------------------------------------
// Tiled SGEMM: C[M,Nc] = act(A[M,K] @ B[K,Nc] + bias)
// BM=BN=64, BK=16, 16x16 threads, 4x4 register tile per thread.
// SRC_A: 0 = use Aarg, 1 = g_h, 2 = g_f (mu columns via lda)
// DST:   0 = g_h, 1 = g_f, 2 = g_ux, 3 = g_umu
// ---------------------------------------------------------------------------
template<int SRC_A, int DST, bool TANH, bool BIAS>
__global__ __launch_bounds__(256) void sgemm_kernel(
    const float* __restrict__ Aarg, const float* __restrict__ Bm,
    const float* __restrict__ bias,
    int M, int Nc, int K, int lda, int ldb, int ldc)
{
    constexpr int BM = 64, BN = 64, BK = 16;
    const float* A = (SRC_A == 1) ? g_h : (SRC_A == 2) ? g_f : Aarg;
    float* C = (DST == 0) ? g_h : (DST == 1) ? g_f : (DST == 2) ? g_ux : g_umu;

    __shared__ float As[BK][BM + 1];   // +1 pad: reduce store conflicts
    __shared__ float Bs[BK][BN];

    const int tx = threadIdx.x;        // 0..15 (N direction)
    const int ty = threadIdx.y;        // 0..15 (M direction)
    const int tid = ty * 16 + tx;
    const int bm = blockIdx.y * BM;
    const int bn = blockIdx.x * BN;

    // A-tile loader: each thread one float4 along K
    const int arow = tid >> 2;          // 0..63
    const int ak4  = (tid & 3) * 4;     // 0,4,8,12
    // B-tile loader: each thread one float4 along N
    const int brow = tid >> 4;          // 0..15
    const int bc4  = (tid & 15) * 4;    // 0..60

    float acc[4][4] = {};

    for (int k0 = 0; k0 < K; k0 += BK) {
        float4 av = *(const float4*)&A[(size_t)(bm + arow) * lda + k0 + ak4];
        As[ak4 + 0][arow] = av.x;
        As[ak4 + 1][arow] = av.y;
        As[ak4 + 2][arow] = av.z;
        As[ak4 + 3][arow] = av.w;
        *(float4*)&Bs[brow][bc4] =
            *(const float4*)&Bm[(size_t)(k0 + brow) * ldb + bn + bc4];
        __syncthreads();

        #pragma unroll
        for (int kk = 0; kk < BK; kk++) {
            float a0 = As[kk][ty * 4 + 0];
            float a1 = As[kk][ty * 4 + 1];
            float a2 = As[kk][ty * 4 + 2];
            float a3 = As[kk][ty * 4 + 3];
            float4 b = *(const float4*)&Bs[kk][tx * 4];
            acc[0][0] += a0 * b.x; acc[0][1] += a0 * b.y; acc[0][2] += a0 * b.z; acc[0][3] += a0 * b.w;
            acc[1][0] += a1 * b.x; acc[1][1] += a1 * b.y; acc[1][2] += a1 * b.z; acc[1][3] += a1 * b.w;
            acc[2][0] += a2 * b.x; acc[2][1] += a2 * b.y; acc[2][2] += a2 * b.z; acc[2][3] += a2 * b.w;
            acc[3][0] += a3 * b.x; acc[3][1] += a3 * b.y; acc[3][2] += a3 * b.z; acc[3][3] += a3 * b.w;
        }
        __syncthreads();
    }

    #pragma unroll
    for (int i = 0; i < 4; i++) {
        const int gm = bm + ty * 4 + i;
        const int gn = bn + tx * 4;
        float4 v;
        v.x = acc[i][0]; v.y = acc[i][1]; v.z = acc[i][2]; v.w = acc[i][3];
        if (BIAS) {
            v.x += bias[gn + 0]; v.y += bias[gn + 1];
            v.z += bias[gn + 2]; v.w += bias[gn + 3];
        }
        if (TANH) {
            v.x = tanhf(v.x); v.y = tanhf(v.y);
            v.z = tanhf(v.z); v.w = tanhf(v.w);
        }
        *(float4*)&C[(size_t)gm * ldc + gn] = v;
    }
}

// ---------------------------------------------------------------------------
// Block-wide (256 threads) sum reduction; result valid in thread 0.
// ---------------------------------------------------------------------------
__device__ __forceinline__ float blockReduce256(float v)
{
    #pragma unroll
    for (int o = 16; o > 0; o >>= 1)
        v += __shfl_down_sync(0xffffffffu, v, o);
    __shared__ float s[8];
    const int lane = threadIdx.x & 31;
    const int w = threadIdx.x >> 5;
    if (lane == 0) s[w] = v;
    __syncthreads();
    if (w == 0) {
        v = (lane < 8) ? s[lane] : 0.0f;
        #pragma unroll
        for (int o = 4; o > 0; o >>= 1)
            v += __shfl_down_sync(0xffffffffu, v, o);
    }
    __syncthreads();   // allow safe reuse of s[] by a second call
    return v;
}

// Vx[r] = sum_j ux[r][j]^2 + 1e-3 ; Vmu[r] likewise
__global__ __launch_bounds__(256) void vreduce_kernel()
{
    const int r = blockIdx.x;
    const int t = threadIdx.x;
    float a = g_ux[r * NN + t];
    float b = g_umu[r * NN + t];
    float sa = blockReduce256(a * a);
    float sb = blockReduce256(b * b);
    if (t == 0) {
        g_Vx[r]  = sa + 1e-3f;
        g_Vmu[r] = sb + 1e-3f;
    }
}

// fx + per-row logp term
__global__ __launch_bounds__(256) void epilogue_kernel(
    const float* __restrict__ y, const float* __restrict__ eps,
    float* __restrict__ out)
{
    const int r = blockIdx.x;
    const int n = threadIdx.x;
    const float mu = g_f[r * N2 + n];
    const float lv = g_f[r * N2 + NN + n];
    const float Vx  = g_Vx[r];
    const float Vmu = g_Vmu[r];
    // bVx - relu(bVx - Vmu) == min(beta*Vx, Vmu)
    const float scale = fminf(0.99f * Vx, Vmu) / Vmu;
    const float mus = mu * scale;
    const float var = expf(lv);
    const float sd  = expf(0.5f * lv);
    out[(size_t)r * NN + n] = mus + sd * eps[(size_t)r * NN + n];
    const float d = y[(size_t)r * NN + n] - mus;
    const float s = blockReduce256(lv + d * d / var);
    if (n == 0)
        g_rowlogp[r] = 0.5f * ((float)NN * LOG2PI + s);
}

// logp_y = sum_r rowlogp[r]  (fixed-order, deterministic)
__global__ __launch_bounds__(256) void finalsum_kernel(float* __restrict__ out,
                                                       int out_size)
{
    float s = 0.0f;
    for (int i = threadIdx.x; i < BB; i += 256)
        s += g_rowlogp[i];
    s = blockReduce256(s);
    if (threadIdx.x == 0)
        out[out_size - 1] = s;
}

// ---------------------------------------------------------------------------
extern "C" void kernel_launch(void* const* d_in, const int* in_sizes, int n_in,
                              void* d_out, int out_size)
{
    const float* x   = (const float*)d_in[0];   // [B,N]
    const float* y   = (const float*)d_in[1];   // [B,1,N]
    const float* eps = (const float*)d_in[2];   // [B,1,N]
    const float* W1  = (const float*)d_in[3];   // [N,H]
    const float* b1  = (const float*)d_in[4];   // [H]
    const float* W2  = (const float*)d_in[5];   // [H,2N]
    const float* b2  = (const float*)d_in[6];   // [2N]
    const float* Wv  = (const float*)d_in[7];   // [N,N]
    float* out = (float*)d_out;

    dim3 blk(16, 16);

    // h = tanh(x @ W1 + b1)           M=8192, Nc=2048, K=256
    sgemm_kernel<0, 0, true, true><<<dim3(HH / 64, BB / 64), blk>>>(
        x, W1, b1, BB, HH, NN, NN, HH, HH);

    // f = h @ W2 + b2                 M=8192, Nc=512, K=2048
    sgemm_kernel<1, 1, false, true><<<dim3(N2 / 64, BB / 64), blk>>>(
        nullptr, W2, b2, BB, N2, HH, HH, N2, N2);

    // ux = x @ Wv                     M=8192, Nc=256, K=256
    sgemm_kernel<0, 2, false, false><<<dim3(NN / 64, BB / 64), blk>>>(
        x, Wv, nullptr, BB, NN, NN, NN, NN, NN);

    // umu = mu @ Wv  (mu = f[:, :256], lda = 512)
    sgemm_kernel<2, 3, false, false><<<dim3(NN / 64, BB / 64), blk>>>(
        nullptr, Wv, nullptr, BB, NN, NN, N2, NN, NN);

    // Vx, Vmu
    vreduce_kernel<<<BB, 256>>>();

    // fx + per-row logp
    epilogue_kernel<<<BB, 256>>>(y, eps, out);

    // scalar logp_y at the tail of the output buffer
    finalsum_kernel<<<1, 256>>>(out, out_size);
}

// round 4
// speedup vs baseline: 2.4429x; 2.4429x over previous
#include <cuda_runtime.h>
#include <math.h>
#include <stdint.h>

// Problem constants
#define BB 8192
#define NN 256
#define HH 2048
#define N2 512
#define LOG2PI 1.8378770664093453f

// Scratch (static __device__ — no runtime allocation)
__device__ float g_h[BB * HH];      // 64 MB  tanh(x@W1+b1), tf32-rounded
__device__ float g_f[BB * N2];      // 16 MB  [mu | logvar], full fp32
__device__ float g_ux[BB * NN];     //  8 MB  x@Wv
__device__ float g_umu[BB * NN];    //  8 MB  mu@Wv
__device__ float g_Vx[BB];
__device__ float g_Vmu[BB];
__device__ float g_rowlogp[BB];
// tf32-rounded copies of inputs
__device__ float g_xr[BB * NN];     //  8 MB
__device__ float g_W1r[NN * HH];    //  2 MB
__device__ float g_W2r[HH * N2];    //  4 MB
__device__ float g_Wvr[NN * NN];    // 256 KB

__device__ __forceinline__ float tf32r(float x) {
    uint32_t t;
    asm("cvt.rna.tf32.f32 %0, %1;" : "=r"(t) : "f"(x));
    return __uint_as_float(t);
}

__device__ __forceinline__ void mma_tf32(float (&c)[4],
    uint32_t a0, uint32_t a1, uint32_t a2, uint32_t a3,
    uint32_t b0, uint32_t b1)
{
    asm volatile(
        "mma.sync.aligned.m16n8k8.row.col.f32.tf32.tf32.f32 "
        "{%0,%1,%2,%3}, {%4,%5,%6,%7}, {%8,%9}, {%0,%1,%2,%3};"
        : "+f"(c[0]), "+f"(c[1]), "+f"(c[2]), "+f"(c[3])
        : "r"(a0), "r"(a1), "r"(a2), "r"(a3), "r"(b0), "r"(b1));
}

// ---------------------------------------------------------------------------
// tf32 MMA GEMM: C[M,Nc] = act(A[M,K] @ B[K,Nc] + bias)
// Block 128x128, BK=32, 256 threads (8 warps), warp tile 64x32.
// SRC_A: 0 = Aarg, 1 = g_h, 2 = g_f(mu, lda=512)
// DST:   0 = g_h (tanh, tf32-rounded store), 1 = g_f, 2 = g_ux, 3 = g_umu
// CVT_A: round A fragments to tf32 in-register (for non-prerounded A)
// ---------------------------------------------------------------------------
template<int SRC_A, int DST, bool TANH, bool BIAS, bool CVT_A>
__global__ __launch_bounds__(256, 2) void mma_gemm(
    const float* __restrict__ Aarg, const float* __restrict__ Bm,
    const float* __restrict__ bias,
    int M, int Nc, int K, int lda, int ldb, int ldc)
{
    constexpr int BM = 128, BN = 128, BK = 32;
    const float* A = (SRC_A == 1) ? g_h : (SRC_A == 2) ? g_f : Aarg;
    float* C = (DST == 0) ? g_h : (DST == 1) ? g_f : (DST == 2) ? g_ux : g_umu;

    __shared__ float As[BK][BM + 8];   // [k][m], pad 8 -> conflict-free frags
    __shared__ float Bs[BK][BN + 8];   // [k][n]

    const int tid  = threadIdx.x;
    const int lane = tid & 31;
    const int w    = tid >> 5;        // 0..7
    const int wm   = (w >> 2) * 64;   // warp M offset: 0 or 64
    const int wn   = (w & 3) * 32;    // warp N offset: 0..96
    const int bm = blockIdx.y * BM;
    const int bn = blockIdx.x * BN;

    const int lr = lane >> 2;         // 0..7
    const int lc = lane & 3;          // 0..3

    float acc[4][4][4] = {};

    for (int k0 = 0; k0 < K; k0 += BK) {
        // Load A tile (BM x BK) transposed into As[k][m]
        #pragma unroll
        for (int i = 0; i < 4; i++) {
            int f  = tid + i * 256;           // 0..1023
            int m  = f >> 3;                  // 0..127
            int kc = (f & 7) * 4;             // 0..28
            float4 v = *(const float4*)&A[(size_t)(bm + m) * lda + k0 + kc];
            As[kc + 0][m] = v.x;
            As[kc + 1][m] = v.y;
            As[kc + 2][m] = v.z;
            As[kc + 3][m] = v.w;
        }
        // Load B tile (BK x BN) into Bs[k][n]
        #pragma unroll
        for (int i = 0; i < 4; i++) {
            int f  = tid + i * 256;
            int k  = f >> 5;                  // 0..31
            int nc = (f & 31) * 4;            // 0..124
            *(float4*)&Bs[k][nc] =
                *(const float4*)&Bm[(size_t)(k0 + k) * ldb + bn + nc];
        }
        __syncthreads();

        #pragma unroll
        for (int ks = 0; ks < 4; ks++) {
            const int kb = ks * 8;
            uint32_t af[4][4];
            #pragma unroll
            for (int mt = 0; mt < 4; mt++) {
                const int mr = wm + mt * 16 + lr;
                float a0 = As[kb + lc    ][mr];
                float a1 = As[kb + lc    ][mr + 8];
                float a2 = As[kb + lc + 4][mr];
                float a3 = As[kb + lc + 4][mr + 8];
                if (CVT_A) { a0 = tf32r(a0); a1 = tf32r(a1);
                             a2 = tf32r(a2); a3 = tf32r(a3); }
                af[mt][0] = __float_as_uint(a0);
                af[mt][1] = __float_as_uint(a1);
                af[mt][2] = __float_as_uint(a2);
                af[mt][3] = __float_as_uint(a3);
            }
            uint32_t bf[4][2];
            #pragma unroll
            for (int nt = 0; nt < 4; nt++) {
                const int ncb = wn + nt * 8 + lr;
                bf[nt][0] = __float_as_uint(Bs[kb + lc    ][ncb]);
                bf[nt][1] = __float_as_uint(Bs[kb + lc + 4][ncb]);
            }
            #pragma unroll
            for (int mt = 0; mt < 4; mt++)
                #pragma unroll
                for (int nt = 0; nt < 4; nt++)
                    mma_tf32(acc[mt][nt],
                             af[mt][0], af[mt][1], af[mt][2], af[mt][3],
                             bf[nt][0], bf[nt][1]);
        }
        __syncthreads();
    }

    // Epilogue: c0,c1 -> (row, col..col+1); c2,c3 -> (row+8, col..col+1)
    #pragma unroll
    for (int mt = 0; mt < 4; mt++) {
        #pragma unroll
        for (int nt = 0; nt < 4; nt++) {
            const int gm = bm + wm + mt * 16 + lr;
            const int gn = bn + wn + nt * 8 + lc * 2;
            float2 v0 = make_float2(acc[mt][nt][0], acc[mt][nt][1]);
            float2 v1 = make_float2(acc[mt][nt][2], acc[mt][nt][3]);
            if (BIAS) {
                const float q0 = bias[gn], q1 = bias[gn + 1];
                v0.x += q0; v0.y += q1;
                v1.x += q0; v1.y += q1;
            }
            if (TANH) {
                v0.x = tf32r(tanhf(v0.x)); v0.y = tf32r(tanhf(v0.y));
                v1.x = tf32r(tanhf(v1.x)); v1.y = tf32r(tanhf(v1.y));
            }
            *(float2*)&C[(size_t)gm * ldc + gn]       = v0;
            *(float2*)&C[(size_t)(gm + 8) * ldc + gn] = v1;
        }
    }
}

// ---------------------------------------------------------------------------
// tf32 pre-rounding (vectorized)
// ---------------------------------------------------------------------------
__global__ __launch_bounds__(256) void round_tf32_kernel(
    const float4* __restrict__ in, float4* __restrict__ out, int n4)
{
    int i = blockIdx.x * 256 + threadIdx.x;
    if (i < n4) {
        float4 v = in[i];
        v.x = tf32r(v.x); v.y = tf32r(v.y);
        v.z = tf32r(v.z); v.w = tf32r(v.w);
        out[i] = v;
    }
}

// ---------------------------------------------------------------------------
__device__ __forceinline__ float blockReduce256(float v)
{
    #pragma unroll
    for (int o = 16; o > 0; o >>= 1)
        v += __shfl_down_sync(0xffffffffu, v, o);
    __shared__ float s[8];
    const int lane = threadIdx.x & 31;
    const int w = threadIdx.x >> 5;
    if (lane == 0) s[w] = v;
    __syncthreads();
    if (w == 0) {
        v = (lane < 8) ? s[lane] : 0.0f;
        #pragma unroll
        for (int o = 4; o > 0; o >>= 1)
            v += __shfl_down_sync(0xffffffffu, v, o);
    }
    __syncthreads();
    return v;
}

__global__ __launch_bounds__(256) void vreduce_kernel()
{
    const int r = blockIdx.x;
    const int t = threadIdx.x;
    float a = g_ux[r * NN + t];
    float b = g_umu[r * NN + t];
    float sa = blockReduce256(a * a);
    float sb = blockReduce256(b * b);
    if (t == 0) {
        g_Vx[r]  = sa + 1e-3f;
        g_Vmu[r] = sb + 1e-3f;
    }
}

__global__ __launch_bounds__(256) void epilogue_kernel(
    const float* __restrict__ y, const float* __restrict__ eps,
    float* __restrict__ out)
{
    const int r = blockIdx.x;
    const int n = threadIdx.x;
    const float mu = g_f[r * N2 + n];
    const float lv = g_f[r * N2 + NN + n];
    const float Vx  = g_Vx[r];
    const float Vmu = g_Vmu[r];
    const float scale = fminf(0.99f * Vx, Vmu) / Vmu;   // == bVx - relu(bVx-Vmu), /Vmu
    const float mus = mu * scale;
    const float var = expf(lv);
    const float sd  = expf(0.5f * lv);
    out[(size_t)r * NN + n] = mus + sd * eps[(size_t)r * NN + n];
    const float d = y[(size_t)r * NN + n] - mus;
    const float s = blockReduce256(lv + d * d / var);
    if (n == 0)
        g_rowlogp[r] = 0.5f * ((float)NN * LOG2PI + s);
}

__global__ __launch_bounds__(256) void finalsum_kernel(float* __restrict__ out,
                                                       int out_size)
{
    float s = 0.0f;
    for (int i = threadIdx.x; i < BB; i += 256)
        s += g_rowlogp[i];
    s = blockReduce256(s);
    if (threadIdx.x == 0)
        out[out_size - 1] = s;
}

// ---------------------------------------------------------------------------
extern "C" void kernel_launch(void* const* d_in, const int* in_sizes, int n_in,
                              void* d_out, int out_size)
{
    const float* x   = (const float*)d_in[0];   // [B,N]
    const float* y   = (const float*)d_in[1];   // [B,1,N]
    const float* eps = (const float*)d_in[2];   // [B,1,N]
    const float* W1  = (const float*)d_in[3];   // [N,H]
    const float* b1  = (const float*)d_in[4];   // [H]
    const float* W2  = (const float*)d_in[5];   // [H,2N]
    const float* b2  = (const float*)d_in[6];   // [2N]
    const float* Wv  = (const float*)d_in[7];   // [N,N]
    float* out = (float*)d_out;

    float *xr, *W1r, *W2r, *Wvr;
    cudaGetSymbolAddress((void**)&xr,  g_xr);
    cudaGetSymbolAddress((void**)&W1r, g_W1r);
    cudaGetSymbolAddress((void**)&W2r, g_W2r);
    cudaGetSymbolAddress((void**)&Wvr, g_Wvr);

    // Pre-round inputs to tf32
    round_tf32_kernel<<<(BB * NN / 4 + 255) / 256, 256>>>((const float4*)x,  (float4*)xr,  BB * NN / 4);
    round_tf32_kernel<<<(NN * HH / 4 + 255) / 256, 256>>>((const float4*)W1, (float4*)W1r, NN * HH / 4);
    round_tf32_kernel<<<(HH * N2 / 4 + 255) / 256, 256>>>((const float4*)W2, (float4*)W2r, HH * N2 / 4);
    round_tf32_kernel<<<(NN * NN / 4 + 255) / 256, 256>>>((const float4*)Wv, (float4*)Wvr, NN * NN / 4);

    // h = tf32(tanh(x @ W1 + b1))   M=8192, Nc=2048, K=256
    mma_gemm<0, 0, true, true, false><<<dim3(HH / 128, BB / 128), 256>>>(
        xr, W1r, b1, BB, HH, NN, NN, HH, HH);

    // f = h @ W2 + b2               M=8192, Nc=512, K=2048
    mma_gemm<1, 1, false, true, false><<<dim3(N2 / 128, BB / 128), 256>>>(
        nullptr, W2r, b2, BB, N2, HH, HH, N2, N2);

    // ux = x @ Wv                   M=8192, Nc=256, K=256
    mma_gemm<0, 2, false, false, false><<<dim3(NN / 128, BB / 128), 256>>>(
        xr, Wvr, nullptr, BB, NN, NN, NN, NN, NN);

    // umu = mu @ Wv  (mu = f[:, :256], lda = 512; round A in-register)
    mma_gemm<2, 3, false, false, true><<<dim3(NN / 128, BB / 128), 256>>>(
        nullptr, Wvr, nullptr, BB, NN, NN, N2, NN, NN);

    // Vx, Vmu
    vreduce_kernel<<<BB, 256>>>();

    // fx + per-row logp
    epilogue_kernel<<<BB, 256>>>(y, eps, out);

    // scalar logp_y at the tail of the output buffer
    finalsum_kernel<<<1, 256>>>(out, out_size);
}

// round 8
// speedup vs baseline: 3.6317x; 1.4867x over previous
#include <cuda_runtime.h>
#include <math.h>
#include <stdint.h>

// Problem constants
#define BB 8192
#define NN 256
#define HH 2048
#define N2 512
#define LOG2PI 1.8378770664093453f

#define AS_STRIDE 36                    // 32 + 4 pad (144B rows, 16B aligned)
#define BS_STRIDE 136                   // 128 + 8 pad (544B rows, 16B aligned)
#define STAGE_FLOATS (128 * AS_STRIDE + 32 * BS_STRIDE)   // 8960
#define SMEM_BYTES (2 * STAGE_FLOATS * 4)                 // 71680

// Scratch (static __device__ — no runtime allocation)
__device__ float g_h[BB * HH];      // tanh(x@W1+b1), tf32-rounded
__device__ float g_f[BB * N2];      // [mu | logvar], tf32-rounded
__device__ float g_ux[BB * NN];
__device__ float g_umu[BB * NN];
__device__ float g_Vx[BB];
__device__ float g_Vmu[BB];
__device__ float g_rowlogp[BB];
__device__ float g_xr[BB * NN];     // tf32-rounded inputs
__device__ float g_W1r[NN * HH];
__device__ float g_W2r[HH * N2];
__device__ float g_Wvr[NN * NN];

__device__ __forceinline__ float tf32r(float x) {
    uint32_t t;
    asm("cvt.rna.tf32.f32 %0, %1;" : "=r"(t) : "f"(x));
    return __uint_as_float(t);
}

__device__ __forceinline__ void mma_tf32(float (&c)[4],
    uint32_t a0, uint32_t a1, uint32_t a2, uint32_t a3,
    uint32_t b0, uint32_t b1)
{
    asm volatile(
        "mma.sync.aligned.m16n8k8.row.col.f32.tf32.tf32.f32 "
        "{%0,%1,%2,%3}, {%4,%5,%6,%7}, {%8,%9}, {%0,%1,%2,%3};"
        : "+f"(c[0]), "+f"(c[1]), "+f"(c[2]), "+f"(c[3])
        : "r"(a0), "r"(a1), "r"(a2), "r"(a3), "r"(b0), "r"(b1));
}

__device__ __forceinline__ void cpasync16(void* dst, const void* src) {
    unsigned s = (unsigned)__cvta_generic_to_shared(dst);
    asm volatile("cp.async.cg.shared.global [%0], [%1], 16;"
                 :: "r"(s), "l"(src));
}

struct Cfg {
    const float* A; const float* B; const float* bias; float* C;
    int K, lda, ldb, ldc, bn;
    bool do_tanh, do_bias, do_round;
};

// ---------------------------------------------------------------------------
// tf32 MMA GEMM body. Block 128x128, BK=32, 8 warps, warp tile 64x32.
// 2-stage cp.async pipeline. As[m][k] (stride 36), Bs[k][n] (stride 136):
// both fragment-load patterns are bank-conflict-free.
// ---------------------------------------------------------------------------
__device__ __forceinline__ void gemm_body(const Cfg& c, float* sm)
{
    const int tid  = threadIdx.x;
    const int lane = tid & 31;
    const int w    = tid >> 5;
    const int wm   = (w >> 2) * 64;
    const int wn   = (w & 3) * 32;
    const int bm   = blockIdx.y * 128;
    const int lr   = lane >> 2;
    const int lc   = lane & 3;
    const int nIter = c.K / 32;

    auto loadTile = [&](int it, int buf) {
        float* As = sm + buf * STAGE_FLOATS;
        float* Bs = As + 128 * AS_STRIDE;
        const int k0 = it * 32;
        #pragma unroll
        for (int i = 0; i < 4; i++) {
            int ch = tid + i * 256;
            int m = ch >> 3, kc = (ch & 7) * 4;
            cpasync16(&As[m * AS_STRIDE + kc],
                      &c.A[(size_t)(bm + m) * c.lda + k0 + kc]);
        }
        #pragma unroll
        for (int i = 0; i < 4; i++) {
            int ch = tid + i * 256;
            int k = ch >> 5, nc = (ch & 31) * 4;
            cpasync16(&Bs[k * BS_STRIDE + nc],
                      &c.B[(size_t)(k0 + k) * c.ldb + c.bn + nc]);
        }
        asm volatile("cp.async.commit_group;" ::);
    };

    float acc[4][4][4] = {};
    loadTile(0, 0);

    for (int it = 0; it < nIter; ++it) {
        asm volatile("cp.async.wait_group 0;" ::);
        __syncthreads();
        if (it + 1 < nIter) loadTile(it + 1, (it + 1) & 1);

        const float* As = sm + (it & 1) * STAGE_FLOATS;
        const float* Bs = As + 128 * AS_STRIDE;

        #pragma unroll
        for (int ks = 0; ks < 4; ks++) {
            const int kb = ks * 8;
            uint32_t af[4][4], bf[4][2];
            #pragma unroll
            for (int mt = 0; mt < 4; mt++) {
                const int mr = wm + mt * 16 + lr;
                af[mt][0] = __float_as_uint(As[mr * AS_STRIDE + kb + lc]);
                af[mt][1] = __float_as_uint(As[(mr + 8) * AS_STRIDE + kb + lc]);
                af[mt][2] = __float_as_uint(As[mr * AS_STRIDE + kb + lc + 4]);
                af[mt][3] = __float_as_uint(As[(mr + 8) * AS_STRIDE + kb + lc + 4]);
            }
            #pragma unroll
            for (int nt = 0; nt < 4; nt++) {
                const int ncb = wn + nt * 8 + lr;
                bf[nt][0] = __float_as_uint(Bs[(kb + lc) * BS_STRIDE + ncb]);
                bf[nt][1] = __float_as_uint(Bs[(kb + lc + 4) * BS_STRIDE + ncb]);
            }
            #pragma unroll
            for (int mt = 0; mt < 4; mt++)
                #pragma unroll
                for (int nt = 0; nt < 4; nt++)
                    mma_tf32(acc[mt][nt],
                             af[mt][0], af[mt][1], af[mt][2], af[mt][3],
                             bf[nt][0], bf[nt][1]);
        }
        __syncthreads();
    }

    #pragma unroll
    for (int mt = 0; mt < 4; mt++) {
        #pragma unroll
        for (int nt = 0; nt < 4; nt++) {
            const int gm = bm + wm + mt * 16 + lr;
            const int gn = c.bn + wn + nt * 8 + lc * 2;
            float2 v0 = make_float2(acc[mt][nt][0], acc[mt][nt][1]);
            float2 v1 = make_float2(acc[mt][nt][2], acc[mt][nt][3]);
            if (c.do_bias) {
                const float q0 = c.bias[gn], q1 = c.bias[gn + 1];
                v0.x += q0; v0.y += q1;
                v1.x += q0; v1.y += q1;
            }
            if (c.do_tanh) {
                v0.x = tanhf(v0.x); v0.y = tanhf(v0.y);
                v1.x = tanhf(v1.x); v1.y = tanhf(v1.y);
            }
            if (c.do_round) {
                v0.x = tf32r(v0.x); v0.y = tf32r(v0.y);
                v1.x = tf32r(v1.x); v1.y = tf32r(v1.y);
            }
            *(float2*)&c.C[(size_t)gm * c.ldc + gn]       = v0;
            *(float2*)&c.C[(size_t)(gm + 8) * c.ldc + gn] = v1;
        }
    }
}

// GEMM1 (h = tf32(tanh(x@W1+b1))) fused with ux = x@Wv — same A, same K.
__global__ __launch_bounds__(256, 2) void k_gemm1_fused(
    const float* __restrict__ xr, const float* __restrict__ W1r,
    const float* __restrict__ b1, const float* __restrict__ Wvr)
{
    extern __shared__ float sm[];
    Cfg c;
    c.A = xr; c.lda = NN; c.K = NN;
    if (blockIdx.x < 16) {
        c.B = W1r; c.ldb = HH; c.bias = b1; c.C = g_h; c.ldc = HH;
        c.bn = blockIdx.x * 128;
        c.do_tanh = true; c.do_bias = true; c.do_round = true;
    } else {
        c.B = Wvr; c.ldb = NN; c.bias = nullptr; c.C = g_ux; c.ldc = NN;
        c.bn = (blockIdx.x - 16) * 128;
        c.do_tanh = false; c.do_bias = false; c.do_round = false;
    }
    gemm_body(c, sm);
}

// GEMM2: f = tf32(h@W2 + b2)
__global__ __launch_bounds__(256, 2) void k_gemm2(
    const float* __restrict__ W2r, const float* __restrict__ b2)
{
    extern __shared__ float sm[];
    Cfg c;
    c.A = g_h; c.lda = HH; c.K = HH;
    c.B = W2r; c.ldb = N2; c.bias = b2; c.C = g_f; c.ldc = N2;
    c.bn = blockIdx.x * 128;
    c.do_tanh = false; c.do_bias = true; c.do_round = true;
    gemm_body(c, sm);
}

// umu = mu @ Wv  (mu = g_f[:, :256], tf32 already rounded at store)
__global__ __launch_bounds__(256, 2) void k_umu(const float* __restrict__ Wvr)
{
    extern __shared__ float sm[];
    Cfg c;
    c.A = g_f; c.lda = N2; c.K = NN;
    c.B = Wvr; c.ldb = NN; c.bias = nullptr; c.C = g_umu; c.ldc = NN;
    c.bn = blockIdx.x * 128;
    c.do_tanh = false; c.do_bias = false; c.do_round = false;
    gemm_body(c, sm);
}

// ---------------------------------------------------------------------------
__global__ __launch_bounds__(256) void round_tf32_kernel(
    const float4* __restrict__ in, float4* __restrict__ out, int n4)
{
    int i = blockIdx.x * 256 + threadIdx.x;
    if (i < n4) {
        float4 v = in[i];
        v.x = tf32r(v.x); v.y = tf32r(v.y);
        v.z = tf32r(v.z); v.w = tf32r(v.w);
        out[i] = v;
    }
}

__device__ __forceinline__ float blockReduce256(float v)
{
    #pragma unroll
    for (int o = 16; o > 0; o >>= 1)
        v += __shfl_down_sync(0xffffffffu, v, o);
    __shared__ float s[8];
    const int lane = threadIdx.x & 31;
    const int w = threadIdx.x >> 5;
    if (lane == 0) s[w] = v;
    __syncthreads();
    if (w == 0) {
        v = (lane < 8) ? s[lane] : 0.0f;
        #pragma unroll
        for (int o = 4; o > 0; o >>= 1)
            v += __shfl_down_sync(0xffffffffu, v, o);
    }
    __syncthreads();
    return v;
}

__global__ __launch_bounds__(256) void vreduce_kernel()
{
    const int r = blockIdx.x;
    const int t = threadIdx.x;
    float a = g_ux[r * NN + t];
    float b = g_umu[r * NN + t];
    float sa = blockReduce256(a * a);
    float sb = blockReduce256(b * b);
    if (t == 0) {
        g_Vx[r]  = sa + 1e-3f;
        g_Vmu[r] = sb + 1e-3f;
    }
}

__global__ __launch_bounds__(256) void epilogue_kernel(
    const float* __restrict__ y, const float* __restrict__ eps,
    float* __restrict__ out)
{
    const int r = blockIdx.x;
    const int n = threadIdx.x;
    const float mu = g_f[r * N2 + n];
    const float lv = g_f[r * N2 + NN + n];
    const float Vx  = g_Vx[r];
    const float Vmu = g_Vmu[r];
    const float scale = fminf(0.99f * Vx, Vmu) / Vmu;   // bVx - relu(bVx-Vmu), /Vmu
    const float mus = mu * scale;
    const float var = expf(lv);
    const float sd  = expf(0.5f * lv);
    out[(size_t)r * NN + n] = mus + sd * eps[(size_t)r * NN + n];
    const float d = y[(size_t)r * NN + n] - mus;
    const float s = blockReduce256(lv + d * d / var);
    if (n == 0)
        g_rowlogp[r] = 0.5f * ((float)NN * LOG2PI + s);
}

__global__ __launch_bounds__(256) void finalsum_kernel(float* __restrict__ out,
                                                       int out_size)
{
    float s = 0.0f;
    for (int i = threadIdx.x; i < BB; i += 256)
        s += g_rowlogp[i];
    s = blockReduce256(s);
    if (threadIdx.x == 0)
        out[out_size - 1] = s;
}

// ---------------------------------------------------------------------------
extern "C" void kernel_launch(void* const* d_in, const int* in_sizes, int n_in,
                              void* d_out, int out_size)
{
    const float* x   = (const float*)d_in[0];
    const float* y   = (const float*)d_in[1];
    const float* eps = (const float*)d_in[2];
    const float* W1  = (const float*)d_in[3];
    const float* b1  = (const float*)d_in[4];
    const float* W2  = (const float*)d_in[5];
    const float* b2  = (const float*)d_in[6];
    const float* Wv  = (const float*)d_in[7];
    float* out = (float*)d_out;

    float *xr, *W1r, *W2r, *Wvr;
    cudaGetSymbolAddress((void**)&xr,  g_xr);
    cudaGetSymbolAddress((void**)&W1r, g_W1r);
    cudaGetSymbolAddress((void**)&W2r, g_W2r);
    cudaGetSymbolAddress((void**)&Wvr, g_Wvr);

    cudaFuncSetAttribute(k_gemm1_fused,
        cudaFuncAttributeMaxDynamicSharedMemorySize, SMEM_BYTES);
    cudaFuncSetAttribute(k_gemm2,
        cudaFuncAttributeMaxDynamicSharedMemorySize, SMEM_BYTES);
    cudaFuncSetAttribute(k_umu,
        cudaFuncAttributeMaxDynamicSharedMemorySize, SMEM_BYTES);

    // Pre-round inputs to tf32 (enables raw cp.async in all GEMMs)
    round_tf32_kernel<<<(BB * NN / 4 + 255) / 256, 256>>>((const float4*)x,  (float4*)xr,  BB * NN / 4);
    round_tf32_kernel<<<(NN * HH / 4 + 255) / 256, 256>>>((const float4*)W1, (float4*)W1r, NN * HH / 4);
    round_tf32_kernel<<<(HH * N2 / 4 + 255) / 256, 256>>>((const float4*)W2, (float4*)W2r, HH * N2 / 4);
    round_tf32_kernel<<<(NN * NN / 4 + 255) / 256, 256>>>((const float4*)Wv, (float4*)Wvr, NN * NN / 4);

    // h = tf32(tanh(x@W1+b1))  [16 col-blocks]  ++  ux = x@Wv  [2 col-blocks]
    k_gemm1_fused<<<dim3(18, BB / 128), 256, SMEM_BYTES>>>(xr, W1r, b1, Wvr);

    // f = tf32(h@W2 + b2)
    k_gemm2<<<dim3(N2 / 128, BB / 128), 256, SMEM_BYTES>>>(W2r, b2);

    // umu = mu @ Wv
    k_umu<<<dim3(NN / 128, BB / 128), 256, SMEM_BYTES>>>(Wvr);

    vreduce_kernel<<<BB, 256>>>();
    epilogue_kernel<<<BB, 256>>>(y, eps, out);
    finalsum_kernel<<<1, 256>>>(out, out_size);
}

// round 11
// speedup vs baseline: 5.6403x; 1.5531x over previous
#include <cuda_runtime.h>
#include <cuda_fp16.h>
#include <math.h>
#include <stdint.h>

// Problem constants
#define BB 8192
#define NN 256
#define HH 2048
#define N2 512
#define LOG2PI 1.8378770664093453f

// Smem: A tile 128 rows x 72 halves (144B, 16B-aligned), B tile same.
#define ROWB 144
#define ASTR 72
#define A_BYTES (128 * ROWB)            // 18432
#define STAGE_BYTES (2 * A_BYTES)       // 36864
#define SMEM_BYTES (2 * STAGE_BYTES)    // 73728

// Scratch (static __device__ — no runtime allocation)
__device__ __half g_h[BB * HH];     // tanh(x@W1+b1), fp16
__device__ float  g_f[BB * N2];     // [mu | logvar], fp32
__device__ __half g_muh[BB * NN];   // fp16 copy of mu (dense, lda=256)
__device__ float  g_ux[BB * NN];
__device__ float  g_umu[BB * NN];
__device__ float  g_rowlogp[BB];
__device__ __half g_xh[BB * NN];    // fp16 x
__device__ __half g_W1t[HH * NN];   // W1^T [2048,256]
__device__ __half g_W2t[N2 * HH];   // W2^T [512,2048]
__device__ __half g_Wvt[NN * NN];   // Wv^T [256,256]

// ---------------------------------------------------------------------------
__device__ __forceinline__ void mma_f16(float (&c)[4],
    uint32_t a0, uint32_t a1, uint32_t a2, uint32_t a3,
    uint32_t b0, uint32_t b1)
{
    asm volatile(
        "mma.sync.aligned.m16n8k16.row.col.f32.f16.f16.f32 "
        "{%0,%1,%2,%3}, {%4,%5,%6,%7}, {%8,%9}, {%0,%1,%2,%3};"
        : "+f"(c[0]), "+f"(c[1]), "+f"(c[2]), "+f"(c[3])
        : "r"(a0), "r"(a1), "r"(a2), "r"(a3), "r"(b0), "r"(b1));
}

__device__ __forceinline__ void cpasync16(uint32_t dst_smem, const void* src) {
    asm volatile("cp.async.cg.shared.global [%0], [%1], 16;"
                 :: "r"(dst_smem), "l"(src));
}

__device__ __forceinline__ uint32_t smem_u32(const void* p) {
    uint32_t a;
    asm("{ .reg .u64 t; cvta.to.shared.u64 t, %1; cvt.u32.u64 %0, t; }"
        : "=r"(a) : "l"(p));
    return a;
}

__device__ __forceinline__ uint32_t ld_h2(const __half* p) {
    return *(const uint32_t*)p;
}

// ---------------------------------------------------------------------------
// fp16 MMA GEMM body. Block 128x128, BK=64, 8 warps, warp tile 64x32.
// C = act(A[M,K] @ Bt[N,K]^T + bias). 2-stage cp.async pipeline.
// MODE: 0 = h (bias+tanh, fp16 store), 1 = ux (fp32 store),
//       2 = f (bias, fp32 store + fp16 mu copy for gn<256), 3 = umu (fp32)
// ---------------------------------------------------------------------------
struct GCfg {
    const __half* A;  int lda;
    const __half* Bt; int ldbt;
    const float* bias;
    int bn, K;
};

template<int MODE>
__device__ __forceinline__ void gemm_body(const GCfg& g)
{
    extern __shared__ char smem[];
    const uint32_t sbase = smem_u32(smem);
    const int tid  = threadIdx.x;
    const int lane = tid & 31;
    const int w    = tid >> 5;
    const int wm   = (w >> 2) * 64;
    const int wn   = (w & 3) * 32;
    const int bm   = blockIdx.y * 128;
    const int lr   = lane >> 2;
    const int lc   = lane & 3;
    const int nIter = g.K / 64;

    auto loadTile = [&](int it) {
        const int k0 = it * 64;
        const uint32_t ab = sbase + (it & 1) * STAGE_BYTES;
        const uint32_t bb = ab + A_BYTES;
        #pragma unroll
        for (int i = 0; i < 4; i++) {           // A: 128 rows x 128B
            int ch = tid + i * 256;
            int r = ch >> 3, c = ch & 7;
            cpasync16(ab + r * ROWB + c * 16,
                      g.A + (size_t)(bm + r) * g.lda + k0 + c * 8);
        }
        #pragma unroll
        for (int i = 0; i < 4; i++) {           // B: 128 rows x 128B
            int ch = tid + i * 256;
            int r = ch >> 3, c = ch & 7;
            cpasync16(bb + r * ROWB + c * 16,
                      g.Bt + (size_t)(g.bn + r) * g.ldbt + k0 + c * 8);
        }
        asm volatile("cp.async.commit_group;" ::);
    };

    float acc[4][4][4] = {};
    loadTile(0);

    for (int it = 0; it < nIter; ++it) {
        asm volatile("cp.async.wait_group 0;" ::);
        __syncthreads();
        if (it + 1 < nIter) loadTile(it + 1);

        const __half* As = (const __half*)(smem + (it & 1) * STAGE_BYTES);
        const __half* Bs = (const __half*)(smem + (it & 1) * STAGE_BYTES + A_BYTES);

        #pragma unroll
        for (int ks = 0; ks < 4; ks++) {
            const int kb = ks * 16;
            uint32_t af[4][4], bf[4][2];
            #pragma unroll
            for (int mt = 0; mt < 4; mt++) {
                const int mr = wm + mt * 16 + lr;
                af[mt][0] = ld_h2(&As[mr * ASTR + kb + 2 * lc]);
                af[mt][1] = ld_h2(&As[(mr + 8) * ASTR + kb + 2 * lc]);
                af[mt][2] = ld_h2(&As[mr * ASTR + kb + 2 * lc + 8]);
                af[mt][3] = ld_h2(&As[(mr + 8) * ASTR + kb + 2 * lc + 8]);
            }
            #pragma unroll
            for (int nt = 0; nt < 4; nt++) {
                const int ncb = wn + nt * 8 + lr;
                bf[nt][0] = ld_h2(&Bs[ncb * ASTR + kb + 2 * lc]);
                bf[nt][1] = ld_h2(&Bs[ncb * ASTR + kb + 2 * lc + 8]);
            }
            #pragma unroll
            for (int mt = 0; mt < 4; mt++)
                #pragma unroll
                for (int nt = 0; nt < 4; nt++)
                    mma_f16(acc[mt][nt],
                            af[mt][0], af[mt][1], af[mt][2], af[mt][3],
                            bf[nt][0], bf[nt][1]);
        }
        __syncthreads();
    }

    // Epilogue
    #pragma unroll
    for (int mt = 0; mt < 4; mt++) {
        #pragma unroll
        for (int nt = 0; nt < 4; nt++) {
            const int gm0 = bm + wm + mt * 16 + lr;
            const int gn  = g.bn + wn + nt * 8 + lc * 2;
            #pragma unroll
            for (int half_row = 0; half_row < 2; half_row++) {
                const int gm = gm0 + half_row * 8;
                float vx = acc[mt][nt][half_row * 2 + 0];
                float vy = acc[mt][nt][half_row * 2 + 1];
                if (MODE == 0 || MODE == 2) {
                    vx += g.bias[gn];
                    vy += g.bias[gn + 1];
                }
                if (MODE == 0) {
                    vx = tanhf(vx); vy = tanhf(vy);
                    *(__half2*)&g_h[(size_t)gm * HH + gn] =
                        __floats2half2_rn(vx, vy);
                } else if (MODE == 1) {
                    *(float2*)&g_ux[(size_t)gm * NN + gn] =
                        make_float2(vx, vy);
                } else if (MODE == 2) {
                    *(float2*)&g_f[(size_t)gm * N2 + gn] =
                        make_float2(vx, vy);
                    if (gn < NN)
                        *(__half2*)&g_muh[(size_t)gm * NN + gn] =
                            __floats2half2_rn(vx, vy);
                } else {
                    *(float2*)&g_umu[(size_t)gm * NN + gn] =
                        make_float2(vx, vy);
                }
            }
        }
    }
}

// GEMM1: h = tanh(x@W1+b1) [16 col-tiles] fused with ux = x@Wv [2 tiles]
__global__ __launch_bounds__(256, 2) void k_gemm1(const float* __restrict__ b1)
{
    GCfg g;
    g.A = g_xh; g.lda = NN; g.K = NN;
    if (blockIdx.x < 16) {
        g.Bt = g_W1t; g.ldbt = NN; g.bias = b1; g.bn = blockIdx.x * 128;
        gemm_body<0>(g);
    } else {
        g.Bt = g_Wvt; g.ldbt = NN; g.bias = nullptr;
        g.bn = (blockIdx.x - 16) * 128;
        gemm_body<1>(g);
    }
}

// GEMM2: f = h@W2 + b2 (fp32) + fp16 mu copy
__global__ __launch_bounds__(256, 2) void k_gemm2(const float* __restrict__ b2)
{
    GCfg g;
    g.A = g_h; g.lda = HH; g.K = HH;
    g.Bt = g_W2t; g.ldbt = HH; g.bias = b2; g.bn = blockIdx.x * 128;
    gemm_body<2>(g);
}

// umu = mu @ Wv  (fp16 mu, dense lda=256)
__global__ __launch_bounds__(256, 2) void k_umu()
{
    GCfg g;
    g.A = g_muh; g.lda = NN; g.K = NN;
    g.Bt = g_Wvt; g.ldbt = NN; g.bias = nullptr; g.bn = blockIdx.x * 128;
    gemm_body<3>(g);
}

// ---------------------------------------------------------------------------
// Operand prep
// ---------------------------------------------------------------------------
__global__ __launch_bounds__(256) void f32_to_h_kernel(
    const float4* __restrict__ in, __half2* __restrict__ out, int n4)
{
    int i = blockIdx.x * 256 + threadIdx.x;
    if (i < n4) {
        float4 v = in[i];
        out[i * 2 + 0] = __floats2half2_rn(v.x, v.y);
        out[i * 2 + 1] = __floats2half2_rn(v.z, v.w);
    }
}

// out[C,R] = half(in[R,C]^T)
__global__ __launch_bounds__(256) void transpose_h_kernel(
    const float* __restrict__ in, __half* __restrict__ out, int R, int C)
{
    __shared__ float t[32][33];
    const int c0 = blockIdx.x * 32, r0 = blockIdx.y * 32;
    #pragma unroll
    for (int j = 0; j < 4; j++)
        t[threadIdx.y + j * 8][threadIdx.x] =
            in[(size_t)(r0 + threadIdx.y + j * 8) * C + c0 + threadIdx.x];
    __syncthreads();
    #pragma unroll
    for (int j = 0; j < 4; j++)
        out[(size_t)(c0 + threadIdx.y + j * 8) * R + r0 + threadIdx.x] =
            __float2half_rn(t[threadIdx.x][threadIdx.y + j * 8]);
}

// ---------------------------------------------------------------------------
__device__ __forceinline__ float blockReduce256(float v)
{
    #pragma unroll
    for (int o = 16; o > 0; o >>= 1)
        v += __shfl_down_sync(0xffffffffu, v, o);
    __shared__ float s[8];
    const int lane = threadIdx.x & 31;
    const int w = threadIdx.x >> 5;
    if (lane == 0) s[w] = v;
    __syncthreads();
    if (w == 0) {
        v = (lane < 8) ? s[lane] : 0.0f;
        #pragma unroll
        for (int o = 4; o > 0; o >>= 1)
            v += __shfl_down_sync(0xffffffffu, v, o);
    }
    __syncthreads();
    return v;
}

// Fused: V reductions + stabilized mean + sample + per-row logp
__global__ __launch_bounds__(256) void fused_epilogue_kernel(
    const float* __restrict__ y, const float* __restrict__ eps,
    float* __restrict__ out)
{
    const int r = blockIdx.x;
    const int n = threadIdx.x;
    const float a = g_ux[r * NN + n];
    const float b = g_umu[r * NN + n];
    const float sa = blockReduce256(a * a);
    const float sb = blockReduce256(b * b);
    __shared__ float sVx, sVmu;
    if (n == 0) { sVx = sa + 1e-3f; sVmu = sb + 1e-3f; }
    __syncthreads();

    const float mu = g_f[r * N2 + n];
    const float lv = g_f[r * N2 + NN + n];
    const float scale = fminf(0.99f * sVx, sVmu) / sVmu;  // bVx-relu(bVx-Vmu), /Vmu
    const float mus = mu * scale;
    const float var = expf(lv);
    const float sd  = expf(0.5f * lv);
    out[(size_t)r * NN + n] = mus + sd * eps[(size_t)r * NN + n];
    const float d = y[(size_t)r * NN + n] - mus;
    const float s = blockReduce256(lv + d * d / var);
    if (n == 0)
        g_rowlogp[r] = 0.5f * ((float)NN * LOG2PI + s);
}

__global__ __launch_bounds__(256) void finalsum_kernel(float* __restrict__ out,
                                                       int out_size)
{
    float s = 0.0f;
    for (int i = threadIdx.x; i < BB; i += 256)
        s += g_rowlogp[i];
    s = blockReduce256(s);
    if (threadIdx.x == 0)
        out[out_size - 1] = s;
}

// ---------------------------------------------------------------------------
extern "C" void kernel_launch(void* const* d_in, const int* in_sizes, int n_in,
                              void* d_out, int out_size)
{
    const float* x   = (const float*)d_in[0];
    const float* y   = (const float*)d_in[1];
    const float* eps = (const float*)d_in[2];
    const float* W1  = (const float*)d_in[3];
    const float* b1  = (const float*)d_in[4];
    const float* W2  = (const float*)d_in[5];
    const float* b2  = (const float*)d_in[6];
    const float* Wv  = (const float*)d_in[7];
    float* out = (float*)d_out;

    __half *xh, *W1t, *W2t, *Wvt;
    cudaGetSymbolAddress((void**)&xh,  g_xh);
    cudaGetSymbolAddress((void**)&W1t, g_W1t);
    cudaGetSymbolAddress((void**)&W2t, g_W2t);
    cudaGetSymbolAddress((void**)&Wvt, g_Wvt);

    cudaFuncSetAttribute(k_gemm1,
        cudaFuncAttributeMaxDynamicSharedMemorySize, SMEM_BYTES);
    cudaFuncSetAttribute(k_gemm2,
        cudaFuncAttributeMaxDynamicSharedMemorySize, SMEM_BYTES);
    cudaFuncSetAttribute(k_umu,
        cudaFuncAttributeMaxDynamicSharedMemorySize, SMEM_BYTES);

    // Operand prep: x -> fp16; weights -> transposed fp16 [N,K]
    f32_to_h_kernel<<<(BB * NN / 4 + 255) / 256, 256>>>(
        (const float4*)x, (__half2*)xh, BB * NN / 4);
    transpose_h_kernel<<<dim3(HH / 32, NN / 32), dim3(32, 8)>>>(W1, W1t, NN, HH);
    transpose_h_kernel<<<dim3(N2 / 32, HH / 32), dim3(32, 8)>>>(W2, W2t, HH, N2);
    transpose_h_kernel<<<dim3(NN / 32, NN / 32), dim3(32, 8)>>>(Wv, Wvt, NN, NN);

    // h = tanh(x@W1+b1) [16 tiles] ++ ux = x@Wv [2 tiles]
    k_gemm1<<<dim3(18, BB / 128), 256, SMEM_BYTES>>>(b1);

    // f = h@W2 + b2 (+ fp16 mu copy)
    k_gemm2<<<dim3(N2 / 128, BB / 128), 256, SMEM_BYTES>>>(b2);

    // umu = mu @ Wv
    k_umu<<<dim3(NN / 128, BB / 128), 256, SMEM_BYTES>>>();

    // V reductions + sample + logp rows, then scalar sum
    fused_epilogue_kernel<<<BB, 256>>>(y, eps, out);
    finalsum_kernel<<<1, 256>>>(out, out_size);
}

// round 12
// speedup vs baseline: 6.3218x; 1.1208x over previous
#include <cuda_runtime.h>
#include <cuda_fp16.h>
#include <math.h>
#include <stdint.h>

// Problem constants
#define BB 8192
#define NN 256
#define HH 2048
#define N2 512
#define LOG2PI 1.8378770664093453f

// Smem: A tile 128 rows x 72 halves (144B rows, 16B-aligned), B tile same.
#define ROWB 144
#define ASTR 72
#define A_BYTES (128 * ROWB)            // 18432
#define STAGE_BYTES (2 * A_BYTES)       // 36864
#define SMEM_BYTES (2 * STAGE_BYTES)    // 73728

// Scratch (static __device__ — no runtime allocation)
__device__ __half g_h[BB * HH];     // tanh(x@W1+b1), fp16
__device__ float  g_f[BB * N2];     // [mu | logvar], fp32
__device__ __half g_muh[BB * NN];   // fp16 copy of mu (dense, lda=256)
__device__ float  g_ux[BB * NN];
__device__ float  g_umu[BB * NN];
__device__ float  g_rowlogp[BB];
__device__ __half g_xh[BB * NN];    // fp16 x
__device__ __half g_W1t[HH * NN];   // W1^T [2048,256]
__device__ __half g_W2t[N2 * HH];   // W2^T [512,2048]
__device__ __half g_Wvt[NN * NN];   // Wv^T [256,256]

// ---------------------------------------------------------------------------
__device__ __forceinline__ void mma_f16(float (&c)[4],
    uint32_t a0, uint32_t a1, uint32_t a2, uint32_t a3,
    uint32_t b0, uint32_t b1)
{
    asm volatile(
        "mma.sync.aligned.m16n8k16.row.col.f32.f16.f16.f32 "
        "{%0,%1,%2,%3}, {%4,%5,%6,%7}, {%8,%9}, {%0,%1,%2,%3};"
        : "+f"(c[0]), "+f"(c[1]), "+f"(c[2]), "+f"(c[3])
        : "r"(a0), "r"(a1), "r"(a2), "r"(a3), "r"(b0), "r"(b1));
}

__device__ __forceinline__ void ldsm_x4(uint32_t (&r)[4], uint32_t addr)
{
    asm volatile(
        "ldmatrix.sync.aligned.m8n8.x4.shared.b16 {%0,%1,%2,%3}, [%4];"
        : "=r"(r[0]), "=r"(r[1]), "=r"(r[2]), "=r"(r[3]) : "r"(addr));
}

__device__ __forceinline__ void cpasync16(uint32_t dst_smem, const void* src) {
    asm volatile("cp.async.cg.shared.global [%0], [%1], 16;"
                 :: "r"(dst_smem), "l"(src));
}

__device__ __forceinline__ uint32_t smem_u32(const void* p) {
    uint32_t a;
    asm("{ .reg .u64 t; cvta.to.shared.u64 t, %1; cvt.u32.u64 %0, t; }"
        : "=r"(a) : "l"(p));
    return a;
}

// ---------------------------------------------------------------------------
// fp16 MMA GEMM body. Block 128x128, BK=64, 8 warps, warp tile 64x32.
// Fragments via ldmatrix.x4. 2-stage cp.async pipeline.
// MODE: 0 = h (bias+tanh, fp16), 1 = ux (fp32), 2 = f (bias, fp32 + fp16 mu),
//       3 = umu (fp32)
// ---------------------------------------------------------------------------
struct GCfg {
    const __half* A;  int lda;
    const __half* Bt; int ldbt;
    const float* bias;
    int bn, K;
};

template<int MODE>
__device__ __forceinline__ void gemm_body(const GCfg& g)
{
    extern __shared__ char smem[];
    const uint32_t sbase = smem_u32(smem);
    const int tid  = threadIdx.x;
    const int lane = tid & 31;
    const int w    = tid >> 5;
    const int wm   = (w >> 2) * 64;
    const int wn   = (w & 3) * 32;
    const int bm   = blockIdx.y * 128;
    const int lr   = lane >> 2;
    const int lc   = lane & 3;
    const int nIter = g.K / 64;

    // ldmatrix per-lane address offsets (bytes, within a stage buffer)
    // A (per mt): row = wm + mt*16 + (lane&7) + ((lane>>3)&1)*8 ; k = ((lane>>4)&1)*8
    const int a_row = (lane & 7) + ((lane >> 3) & 1) * 8;
    const int a_k   = ((lane >> 4) & 1) * 8;
    uint32_t a_off[4];
    #pragma unroll
    for (int mt = 0; mt < 4; mt++)
        a_off[mt] = (uint32_t)(((wm + mt * 16 + a_row) * ASTR + a_k) * 2);
    // B (per pair p): row = wn + p*16 + ((lane>>4)&1)*8 + (lane&7) ; k = ((lane>>3)&1)*8
    const int b_row = ((lane >> 4) & 1) * 8 + (lane & 7);
    const int b_k   = ((lane >> 3) & 1) * 8;
    uint32_t b_off[2];
    #pragma unroll
    for (int p = 0; p < 2; p++)
        b_off[p] = (uint32_t)(A_BYTES + ((wn + p * 16 + b_row) * ASTR + b_k) * 2);

    auto loadTile = [&](int it) {
        const int k0 = it * 64;
        const uint32_t ab = sbase + (it & 1) * STAGE_BYTES;
        const uint32_t bb = ab + A_BYTES;
        #pragma unroll
        for (int i = 0; i < 4; i++) {           // A: 128 rows x 128B
            int ch = tid + i * 256;
            int r = ch >> 3, c = ch & 7;
            cpasync16(ab + r * ROWB + c * 16,
                      g.A + (size_t)(bm + r) * g.lda + k0 + c * 8);
        }
        #pragma unroll
        for (int i = 0; i < 4; i++) {           // B: 128 rows x 128B
            int ch = tid + i * 256;
            int r = ch >> 3, c = ch & 7;
            cpasync16(bb + r * ROWB + c * 16,
                      g.Bt + (size_t)(g.bn + r) * g.ldbt + k0 + c * 8);
        }
        asm volatile("cp.async.commit_group;" ::);
    };

    float acc[4][4][4] = {};
    loadTile(0);

    for (int it = 0; it < nIter; ++it) {
        asm volatile("cp.async.wait_group 0;" ::);
        __syncthreads();
        if (it + 1 < nIter) loadTile(it + 1);

        const uint32_t stage = sbase + (it & 1) * STAGE_BYTES;

        #pragma unroll
        for (int ks = 0; ks < 4; ks++) {
            const uint32_t kadd = stage + ks * 32;   // 16 halves = 32 bytes
            uint32_t af[4][4], bf[4][2];
            #pragma unroll
            for (int mt = 0; mt < 4; mt++)
                ldsm_x4(af[mt], kadd + a_off[mt]);
            #pragma unroll
            for (int p = 0; p < 2; p++) {
                uint32_t r[4];
                ldsm_x4(r, kadd + b_off[p]);
                bf[2 * p][0] = r[0]; bf[2 * p][1] = r[1];
                bf[2 * p + 1][0] = r[2]; bf[2 * p + 1][1] = r[3];
            }
            #pragma unroll
            for (int mt = 0; mt < 4; mt++)
                #pragma unroll
                for (int nt = 0; nt < 4; nt++)
                    mma_f16(acc[mt][nt],
                            af[mt][0], af[mt][1], af[mt][2], af[mt][3],
                            bf[nt][0], bf[nt][1]);
        }
        __syncthreads();
    }

    // Epilogue
    #pragma unroll
    for (int mt = 0; mt < 4; mt++) {
        #pragma unroll
        for (int nt = 0; nt < 4; nt++) {
            const int gm0 = bm + wm + mt * 16 + lr;
            const int gn  = g.bn + wn + nt * 8 + lc * 2;
            #pragma unroll
            for (int hrow = 0; hrow < 2; hrow++) {
                const int gm = gm0 + hrow * 8;
                float vx = acc[mt][nt][hrow * 2 + 0];
                float vy = acc[mt][nt][hrow * 2 + 1];
                if (MODE == 0 || MODE == 2) {
                    vx += g.bias[gn];
                    vy += g.bias[gn + 1];
                }
                if (MODE == 0) {
                    vx = tanhf(vx); vy = tanhf(vy);
                    *(__half2*)&g_h[(size_t)gm * HH + gn] =
                        __floats2half2_rn(vx, vy);
                } else if (MODE == 1) {
                    *(float2*)&g_ux[(size_t)gm * NN + gn] =
                        make_float2(vx, vy);
                } else if (MODE == 2) {
                    *(float2*)&g_f[(size_t)gm * N2 + gn] =
                        make_float2(vx, vy);
                    if (gn < NN)
                        *(__half2*)&g_muh[(size_t)gm * NN + gn] =
                            __floats2half2_rn(vx, vy);
                } else {
                    *(float2*)&g_umu[(size_t)gm * NN + gn] =
                        make_float2(vx, vy);
                }
            }
        }
    }
}

// GEMM1: h = tanh(x@W1+b1) [16 col-tiles] fused with ux = x@Wv [2 tiles]
__global__ __launch_bounds__(256, 2) void k_gemm1(const float* __restrict__ b1)
{
    GCfg g;
    g.A = g_xh; g.lda = NN; g.K = NN;
    if (blockIdx.x < 16) {
        g.Bt = g_W1t; g.ldbt = NN; g.bias = b1; g.bn = blockIdx.x * 128;
        gemm_body<0>(g);
    } else {
        g.Bt = g_Wvt; g.ldbt = NN; g.bias = nullptr;
        g.bn = (blockIdx.x - 16) * 128;
        gemm_body<1>(g);
    }
}

// GEMM2: f = h@W2 + b2 (fp32) + fp16 mu copy
__global__ __launch_bounds__(256, 2) void k_gemm2(const float* __restrict__ b2)
{
    GCfg g;
    g.A = g_h; g.lda = HH; g.K = HH;
    g.Bt = g_W2t; g.ldbt = HH; g.bias = b2; g.bn = blockIdx.x * 128;
    gemm_body<2>(g);
}

// umu = mu @ Wv  (fp16 mu, dense lda=256)
__global__ __launch_bounds__(256, 2) void k_umu()
{
    GCfg g;
    g.A = g_muh; g.lda = NN; g.K = NN;
    g.Bt = g_Wvt; g.ldbt = NN; g.bias = nullptr; g.bn = blockIdx.x * 128;
    gemm_body<3>(g);
}

// ---------------------------------------------------------------------------
// Combined operand prep: all three weight transposes in ONE launch.
// Block ranges: [0,512) W1, [512,1536) W2, [1536,1600) Wv.
// ---------------------------------------------------------------------------
__device__ __forceinline__ void transpose_tile(
    const float* __restrict__ in, __half* __restrict__ out,
    int R, int C, int bx, int by)
{
    __shared__ float t[32][33];
    const int c0 = bx * 32, r0 = by * 32;
    #pragma unroll
    for (int j = 0; j < 4; j++)
        t[threadIdx.y + j * 8][threadIdx.x] =
            in[(size_t)(r0 + threadIdx.y + j * 8) * C + c0 + threadIdx.x];
    __syncthreads();
    #pragma unroll
    for (int j = 0; j < 4; j++)
        out[(size_t)(c0 + threadIdx.y + j * 8) * R + r0 + threadIdx.x] =
            __float2half_rn(t[threadIdx.x][threadIdx.y + j * 8]);
}

__global__ __launch_bounds__(256) void prep_weights_kernel(
    const float* __restrict__ W1, const float* __restrict__ W2,
    const float* __restrict__ Wv)
{
    const int b = blockIdx.x;
    if (b < 512) {          // W1 [256,2048] -> W1t [2048,256]; 64 x 8 tiles
        transpose_tile(W1, g_W1t, NN, HH, b & 63, b >> 6);
    } else if (b < 1536) {  // W2 [2048,512] -> W2t [512,2048]; 16 x 64 tiles
        const int bb = b - 512;
        transpose_tile(W2, g_W2t, HH, N2, bb & 15, bb >> 4);
    } else {                // Wv [256,256] -> Wvt [256,256]; 8 x 8 tiles
        const int bb = b - 1536;
        transpose_tile(Wv, g_Wvt, NN, NN, bb & 7, bb >> 3);
    }
}

__global__ __launch_bounds__(256) void f32_to_h_kernel(
    const float4* __restrict__ in, __half2* __restrict__ out, int n4)
{
    int i = blockIdx.x * 256 + threadIdx.x;
    if (i < n4) {
        float4 v = in[i];
        out[i * 2 + 0] = __floats2half2_rn(v.x, v.y);
        out[i * 2 + 1] = __floats2half2_rn(v.z, v.w);
    }
}

// ---------------------------------------------------------------------------
__device__ __forceinline__ float blockReduce256(float v)
{
    #pragma unroll
    for (int o = 16; o > 0; o >>= 1)
        v += __shfl_down_sync(0xffffffffu, v, o);
    __shared__ float s[8];
    const int lane = threadIdx.x & 31;
    const int w = threadIdx.x >> 5;
    if (lane == 0) s[w] = v;
    __syncthreads();
    if (w == 0) {
        v = (lane < 8) ? s[lane] : 0.0f;
        #pragma unroll
        for (int o = 4; o > 0; o >>= 1)
            v += __shfl_down_sync(0xffffffffu, v, o);
    }
    __syncthreads();
    return v;
}

// Fused: V reductions + stabilized mean + sample + per-row logp
__global__ __launch_bounds__(256) void fused_epilogue_kernel(
    const float* __restrict__ y, const float* __restrict__ eps,
    float* __restrict__ out)
{
    const int r = blockIdx.x;
    const int n = threadIdx.x;
    const float a = g_ux[r * NN + n];
    const float b = g_umu[r * NN + n];
    const float sa = blockReduce256(a * a);
    const float sb = blockReduce256(b * b);
    __shared__ float sVx, sVmu;
    if (n == 0) { sVx = sa + 1e-3f; sVmu = sb + 1e-3f; }
    __syncthreads();

    const float mu = g_f[r * N2 + n];
    const float lv = g_f[r * N2 + NN + n];
    const float scale = fminf(0.99f * sVx, sVmu) / sVmu;  // bVx-relu(bVx-Vmu), /Vmu
    const float mus = mu * scale;
    const float var = expf(lv);
    const float sd  = expf(0.5f * lv);
    out[(size_t)r * NN + n] = mus + sd * eps[(size_t)r * NN + n];
    const float d = y[(size_t)r * NN + n] - mus;
    const float s = blockReduce256(lv + d * d / var);
    if (n == 0)
        g_rowlogp[r] = 0.5f * ((float)NN * LOG2PI + s);
}

__global__ __launch_bounds__(256) void finalsum_kernel(float* __restrict__ out,
                                                       int out_size)
{
    float s = 0.0f;
    for (int i = threadIdx.x; i < BB; i += 256)
        s += g_rowlogp[i];
    s = blockReduce256(s);
    if (threadIdx.x == 0)
        out[out_size - 1] = s;
}

// ---------------------------------------------------------------------------
extern "C" void kernel_launch(void* const* d_in, const int* in_sizes, int n_in,
                              void* d_out, int out_size)
{
    const float* x   = (const float*)d_in[0];
    const float* y   = (const float*)d_in[1];
    const float* eps = (const float*)d_in[2];
    const float* W1  = (const float*)d_in[3];
    const float* b1  = (const float*)d_in[4];
    const float* W2  = (const float*)d_in[5];
    const float* b2  = (const float*)d_in[6];
    const float* Wv  = (const float*)d_in[7];
    float* out = (float*)d_out;

    __half* xh;
    cudaGetSymbolAddress((void**)&xh, g_xh);

    cudaFuncSetAttribute(k_gemm1,
        cudaFuncAttributeMaxDynamicSharedMemorySize, SMEM_BYTES);
    cudaFuncSetAttribute(k_gemm2,
        cudaFuncAttributeMaxDynamicSharedMemorySize, SMEM_BYTES);
    cudaFuncSetAttribute(k_umu,
        cudaFuncAttributeMaxDynamicSharedMemorySize, SMEM_BYTES);

    // Operand prep
    f32_to_h_kernel<<<(BB * NN / 4 + 255) / 256, 256>>>(
        (const float4*)x, (__half2*)xh, BB * NN / 4);
    prep_weights_kernel<<<1600, dim3(32, 8)>>>(W1, W2, Wv);

    // h = tanh(x@W1+b1) [16 tiles] ++ ux = x@Wv [2 tiles]
    k_gemm1<<<dim3(18, BB / 128), 256, SMEM_BYTES>>>(b1);

    // f = h@W2 + b2 (+ fp16 mu copy)
    k_gemm2<<<dim3(N2 / 128, BB / 128), 256, SMEM_BYTES>>>(b2);

    // umu = mu @ Wv
    k_umu<<<dim3(NN / 128, BB / 128), 256, SMEM_BYTES>>>();

    // V reductions + sample + logp rows, then scalar sum
    fused_epilogue_kernel<<<BB, 256>>>(y, eps, out);
    finalsum_kernel<<<1, 256>>>(out, out_size);
}